// round 13
// baseline (speedup 1.0000x reference)
#include <cuda_runtime.h>
#include <cuda_bf16.h>
#include <math_constants.h>

// x = [B=8, C=256, H=128, W=128] fp32
#define B 8
#define C 256
#define H 128
#define W 128
#define HW (H*W)
#define WC 32             // w-chunk per kB block
#define NCH 4             // W / WC

// ---------- scratch ----------
__device__ float g_u[C];
__device__ float g_ub;
__device__ __align__(16) float g_t3[B*HW];
__device__ __align__(16) float g_xkpart[B*H*NCH*C];   // [b][h][chunk][c]
__device__ __align__(16) float g_cfp[B*8*C];          // per-slice cf partial dots
__device__ float g_Zp[B*H*NCH];
__device__ float g_invZ[B];
__device__ float g_cmax[B*H*W];
__device__ float g_csum[B*H*W];
__device__ float g_hmaxp[B*H*NCH];
__device__ float g_hsump[B*H*NCH];
__device__ float g_hatt[B*H];
__device__ float g_watt[B*W];

// ---------- kA: u = w3^T v_w, ub = w3.v_b ----------
__global__ void __launch_bounds__(256) kA(const float* __restrict__ vw,
                                          const float* __restrict__ vb,
                                          const float* __restrict__ w3) {
    __shared__ float red[256];
    int t = threadIdx.x, lane = t & 31, g = t >> 5;
    int c = (blockIdx.x << 5) + lane;
    float u = 0.f;
    #pragma unroll
    for (int o = g; o < C; o += 8) u = fmaf(w3[o], vw[o*C + c], u);
    red[t] = u;
    __syncthreads();
    if (t < 32) {
        float s = 0.f;
        #pragma unroll
        for (int k2 = 0; k2 < 8; k2++) s += red[(k2 << 5) + t];
        g_u[(blockIdx.x << 5) + t] = s;
    }
    if (blockIdx.x == 0) {
        __syncthreads();
        red[t] = w3[t] * vb[t];
        __syncthreads();
        if (t < 32) {
            float s = 0.f;
            #pragma unroll
            for (int k2 = 0; k2 < 8; k2++) s += red[(k2 << 5) + t];
            #pragma unroll
            for (int o = 16; o; o >>= 1) s += __shfl_down_sync(0xffffffffu, s, o);
            if (t == 0) g_ub = s;
        }
    }
}

// ---------- kB: main reduction pass — register-resident ----------
__global__ void __launch_bounds__(256, 4) kB(const float* __restrict__ x,
                                             const float* __restrict__ kw) {
    __shared__ float wsh[C], ush[C];
    __shared__ float red[4*256];
    __shared__ float esh[WC];

    int t = threadIdx.x, lane = t & 31, wid = t >> 5;
    int h = blockIdx.x, chunk = blockIdx.y, b = blockIdx.z;
    wsh[t] = kw[t];
    ush[t] = g_u[t];
    __syncthreads();

    int cloc = lane >> 3, w4 = lane & 7;
    int c0 = (wid << 5) + (cloc << 3);
    const float4* xp = (const float4*)(x + (((size_t)(b*C + c0)) << 14)
                                         + (h << 7) + (chunk << 5)) + w4;

    float4 v[8];
    #pragma unroll
    for (int j = 0; j < 8; j++) v[j] = __ldcs(xp + ((size_t)j << 12));  // +j*HW/4

    float kl[4] = {0,0,0,0}, t3[4] = {0,0,0,0}, sm[4] = {0,0,0,0};
    float mx[4] = {-1e30f,-1e30f,-1e30f,-1e30f};
    #pragma unroll
    for (int j = 0; j < 8; j++) {
        int c = c0 + j;
        float kc = wsh[c], uc = ush[c];
        kl[0]=fmaf(kc,v[j].x,kl[0]); kl[1]=fmaf(kc,v[j].y,kl[1]); kl[2]=fmaf(kc,v[j].z,kl[2]); kl[3]=fmaf(kc,v[j].w,kl[3]);
        t3[0]=fmaf(uc,v[j].x,t3[0]); t3[1]=fmaf(uc,v[j].y,t3[1]); t3[2]=fmaf(uc,v[j].z,t3[2]); t3[3]=fmaf(uc,v[j].w,t3[3]);
        mx[0]=fmaxf(mx[0],v[j].x); mx[1]=fmaxf(mx[1],v[j].y); mx[2]=fmaxf(mx[2],v[j].z); mx[3]=fmaxf(mx[3],v[j].w);
        sm[0]+=v[j].x; sm[1]+=v[j].y; sm[2]+=v[j].z; sm[3]+=v[j].w;
    }
    #pragma unroll
    for (int o = 16; o >= 8; o >>= 1) {
        #pragma unroll
        for (int l = 0; l < 4; l++) {
            kl[l] += __shfl_down_sync(0xffffffffu, kl[l], o);
            t3[l] += __shfl_down_sync(0xffffffffu, t3[l], o);
            mx[l] = fmaxf(mx[l], __shfl_down_sync(0xffffffffu, mx[l], o));
            sm[l] += __shfl_down_sync(0xffffffffu, sm[l], o);
        }
    }
    if (lane < 8) {
        int base = (wid << 5) + (lane << 2);
        #pragma unroll
        for (int l = 0; l < 4; l++) {
            red[base + l]       = kl[l];
            red[256 + base + l] = t3[l];
            red[512 + base + l] = mx[l];
            red[768 + base + l] = sm[l];
        }
    }
    __syncthreads();

    int bh = (b << 7) + h;
    int ci = (bh << 2) + chunk;
    if (t < 32) {
        float klw = 0.f, t3w = 0.f, smw = 0.f, mxw = -1e30f;
        #pragma unroll
        for (int wp = 0; wp < 8; wp++) {
            klw += red[(wp << 5) + t];
            t3w += red[256 + (wp << 5) + t];
            mxw = fmaxf(mxw, red[512 + (wp << 5) + t]);
            smw += red[768 + (wp << 5) + t];
        }
        float e = __expf(klw);                    // klin ~ N(0,1): no shift needed
        esh[t] = e;
        int gi = (bh << 7) + (chunk << 5) + t;
        g_t3[gi]   = t3w + g_ub;
        g_cmax[gi] = mxw;
        g_csum[gi] = smw;
        float rm = mxw, rs = smw, rz = e;
        #pragma unroll
        for (int o = 16; o; o >>= 1) {
            rm = fmaxf(rm, __shfl_down_sync(0xffffffffu, rm, o));
            rs += __shfl_down_sync(0xffffffffu, rs, o);
            rz += __shfl_down_sync(0xffffffffu, rz, o);
        }
        if (t == 0) { g_hmaxp[ci] = rm; g_hsump[ci] = rs; g_Zp[ci] = rz; }
    }
    __syncthreads();

    // phase 2 (register-resident): xk[c] partial
    float e0 = esh[(w4 << 2) + 0], e1 = esh[(w4 << 2) + 1];
    float e2 = esh[(w4 << 2) + 2], e3 = esh[(w4 << 2) + 3];
    float xkp[8];
    #pragma unroll
    for (int j = 0; j < 8; j++)
        xkp[j] = fmaf(v[j].x, e0, fmaf(v[j].y, e1, fmaf(v[j].z, e2, v[j].w * e3)));
    #pragma unroll
    for (int o = 4; o; o >>= 1) {
        #pragma unroll
        for (int j = 0; j < 8; j++)
            xkp[j] += __shfl_down_sync(0xffffffffu, xkp[j], o);
    }
    if (w4 == 0) {
        float* dst = g_xkpart + (((size_t)ci) << 8) + c0;
        #pragma unroll
        for (int j = 0; j < 8; j++) dst[j] = xkp[j];
    }
}

// ---------- kM: merged stage-2 (grid (16,B)) — kCF folded in ----------
// slices 0-7: xkpart slice sum -> smem, then FULL matvec v_w @ slice ->
//             g_cfp[b][slice][*] (distributed cf, assembled in kE).
// slices 8-15: column stats -> g_watt + g_hatt; slice 8 also Z -> g_invZ.
__global__ void __launch_bounds__(256) kM(const float* __restrict__ vw,
                                          const float* __restrict__ w1,
                                          const float* __restrict__ b1,
                                          const float* __restrict__ w2,
                                          const float* __restrict__ b2) {
    int t = threadIdx.x;
    int slice = blockIdx.x, b = blockIdx.y;
    if (slice < 8) {
        __shared__ float xksh[C];
        int lane = t & 31, wid = t >> 5;
        const float* base = g_xkpart + ((size_t)((b << 9) + (slice << 6)) << 8);
        float acc = 0.f;
        #pragma unroll 8
        for (int i = 0; i < 64; i++) acc += base[((size_t)i << 8) + t];
        xksh[t] = acc;
        __syncthreads();

        // full 256-row matvec: warp wid handles rows wid*32 .. wid*32+31
        const float4* vw4 = (const float4*)vw;
        const float4* xk4 = (const float4*)xksh;
        float4 x0 = xk4[lane];
        float4 x1 = xk4[32 + lane];
        float* dst = g_cfp + (((b << 3) + slice) << 8);
        #pragma unroll 4
        for (int r = 0; r < 32; r++) {
            int o = (wid << 5) + r;
            float4 wv0 = vw4[(o << 6) + lane];
            float4 wv1 = vw4[(o << 6) + 32 + lane];
            float a = fmaf(wv0.x, x0.x, fmaf(wv0.y, x0.y, fmaf(wv0.z, x0.z, wv0.w * x0.w)));
            a = fmaf(wv1.x, x1.x, fmaf(wv1.y, x1.y, fmaf(wv1.z, x1.z, fmaf(wv1.w, x1.w, a))));
            #pragma unroll
            for (int o2 = 16; o2; o2 >>= 1) a += __shfl_down_sync(0xffffffffu, a, o2);
            if (lane == 0) dst[o] = a;
        }
    } else {
        __shared__ float rm[256], rs[256];
        __shared__ float zp[8];
        int s2 = slice - 8;
        int w0 = s2 << 4;                        // this block: 16 w columns
        int w = t & 15, hg = t >> 4;             // 16 h-groups of 8 rows

        float zval = 0.f;
        if (s2 == 0)
            zval = g_Zp[(b << 9) + t] + g_Zp[(b << 9) + 256 + t];

        const float* cm = g_cmax + ((size_t)b << 14) + w0 + w;
        const float* cs = g_csum + ((size_t)b << 14) + w0 + w;
        float wm = -1e30f, ws = 0.f;
        #pragma unroll
        for (int i = 0; i < 8; i++) {
            int r = (hg << 3) + i;
            wm = fmaxf(wm, cm[r << 7]);
            ws += cs[r << 7];
        }
        rm[t] = wm; rs[t] = ws;
        if (s2 == 0) {
            #pragma unroll
            for (int o = 16; o; o >>= 1) zval += __shfl_down_sync(0xffffffffu, zval, o);
            if ((t & 31) == 0) zp[t >> 5] = zval;
        }
        __syncthreads();
        if (s2 == 0 && t == 0)
            g_invZ[b] = 1.f / (zp[0]+zp[1]+zp[2]+zp[3]+zp[4]+zp[5]+zp[6]+zp[7]);
        if (t < 16) {
            float m = rm[t], s = rs[t];
            #pragma unroll
            for (int k = 1; k < 16; k++) {
                m = fmaxf(m, rm[(k << 4) + t]);
                s += rs[(k << 4) + t];
            }
            float wa = fmaf(w2[0], m, fmaf(w2[1], s * (1.f/32768.f), b2[0]));
            g_watt[(b << 7) + w0 + t] = 1.f / (1.f + __expf(-wa));

            int h = w0 + t;
            int i4 = ((b << 7) + h) << 2;
            float hm = fmaxf(fmaxf(g_hmaxp[i4], g_hmaxp[i4+1]),
                             fmaxf(g_hmaxp[i4+2], g_hmaxp[i4+3]));
            float hs = g_hsump[i4] + g_hsump[i4+1] + g_hsump[i4+2] + g_hsump[i4+3];
            float ha = fmaf(w1[0], hm, fmaf(w1[1], hs * (1.f/32768.f), b1[0]));
            g_hatt[(b << 7) + h] = 1.f / (1.f + __expf(-ha));
        }
    }
}

// ---------- kE: fused gate + cf assembly + output. out = s*cf + x ----------
__global__ void __launch_bounds__(256) kE(const float* __restrict__ x,
                                          float* __restrict__ out,
                                          const float* __restrict__ vb,
                                          const float* __restrict__ b3) {
    __shared__ float4 s4sh[64];
    __shared__ float cfsh[64];
    int t = threadIdx.x;
    int blk = blockIdx.x;
    int b = blk >> 8, rest = blk & 255;
    int pc = rest >> 2, cq = rest & 3;
    int p0 = pc << 8;
    int cbase = cq << 6;
    if (t < 64) {
        int c = cbase + t;
        float acc = 0.f;
        #pragma unroll
        for (int s = 0; s < 8; s++) acc += g_cfp[(((b << 3) + s) << 8) + c];
        cfsh[t] = fmaf(g_invZ[b], acc, vb[c]);

        float4 t3v = reinterpret_cast<const float4*>(g_t3)[(b << 12) + (p0 >> 2) + t];
        int p = p0 + (t << 2);
        float ha = g_hatt[(b << 7) + (p >> 7)];
        int w0 = p & 127;
        float bb = b3[0];
        float4 s4; float a;
        a = fmaf(ha + g_watt[(b<<7)+w0+0], t3v.x, bb); s4.x = 1.f/(1.f+__expf(-a));
        a = fmaf(ha + g_watt[(b<<7)+w0+1], t3v.y, bb); s4.y = 1.f/(1.f+__expf(-a));
        a = fmaf(ha + g_watt[(b<<7)+w0+2], t3v.z, bb); s4.z = 1.f/(1.f+__expf(-a));
        a = fmaf(ha + g_watt[(b<<7)+w0+3], t3v.w, bb); s4.w = 1.f/(1.f+__expf(-a));
        s4sh[t] = s4;
    }
    __syncthreads();

    int c_off = t >> 6, p4 = t & 63;
    const float4* xb = (const float4*)x + ((size_t)b << 20)
                       + ((size_t)cbase << 12) + (p0 >> 2) + p4;
    float4*       ob = (float4*)out     + ((size_t)b << 20)
                       + ((size_t)cbase << 12) + (p0 >> 2) + p4;
    float4 sv = s4sh[p4];
    #pragma unroll 4
    for (int cb = 0; cb < 64; cb += 4) {
        int c = cb + c_off;
        float4 xv = __ldcs(xb + ((size_t)c << 12));
        float cf = cfsh[c];
        float4 ov;
        ov.x = fmaf(sv.x, cf, xv.x);
        ov.y = fmaf(sv.y, cf, xv.y);
        ov.z = fmaf(sv.z, cf, xv.z);
        ov.w = fmaf(sv.w, cf, xv.w);
        __stcs(ob + ((size_t)c << 12), ov);
    }
}

extern "C" void kernel_launch(void* const* d_in, const int* in_sizes, int n_in,
                              void* d_out, int out_size) {
    const float* x  = (const float*)d_in[0];
    const float* vw = (const float*)d_in[1];
    const float* vb = (const float*)d_in[2];
    const float* kw = (const float*)d_in[3];
    // d_in[4] = k_b: softmax shift-invariant, unused
    const float* w1 = (const float*)d_in[5];
    const float* b1 = (const float*)d_in[6];
    const float* w2 = (const float*)d_in[7];
    const float* b2 = (const float*)d_in[8];
    const float* w3 = (const float*)d_in[9];
    const float* b3 = (const float*)d_in[10];
    float* out = (float*)d_out;

    kA<<<8, 256>>>(vw, vb, w3);
    dim3 gB(H, NCH, B);
    kB<<<gB, 256>>>(x, kw);
    dim3 gM(16, B);
    kM<<<gM, 256>>>(vw, w1, b1, w2, b2);
    kE<<<2048, 256>>>(x, out, vb, b3);
}

// round 14
// speedup vs baseline: 1.0454x; 1.0454x over previous
#include <cuda_runtime.h>
#include <cuda_bf16.h>
#include <math_constants.h>

// x = [B=8, C=256, H=128, W=128] fp32
#define B 8
#define C 256
#define H 128
#define W 128
#define HW (H*W)
#define WC 32             // w-chunk per kB block
#define NCH 4             // W / WC

// ---------- scratch ----------
__device__ float g_u[C];
__device__ float g_ub;
__device__ __align__(16) float g_t3[B*HW];
__device__ __align__(16) float g_xkpart[B*H*NCH*C];   // [b][h][chunk][c]
__device__ __align__(16) float g_xk2[B*8*C];          // slice partials
__device__ float g_Zp[B*H*NCH];
__device__ float g_invZ[B];
__device__ float g_cmax[B*H*W];
__device__ float g_csum[B*H*W];
__device__ float g_hmaxp[B*H*NCH];
__device__ float g_hsump[B*H*NCH];
__device__ float g_hatt[B*H];
__device__ float g_watt[B*W];
__device__ float g_cf[B*C];

// ---------- kA: u = w3^T v_w, ub = w3.v_b ----------
__global__ void __launch_bounds__(256) kA(const float* __restrict__ vw,
                                          const float* __restrict__ vb,
                                          const float* __restrict__ w3) {
    __shared__ float red[256];
    int t = threadIdx.x, lane = t & 31, g = t >> 5;
    int c = (blockIdx.x << 5) + lane;
    float u = 0.f;
    #pragma unroll
    for (int o = g; o < C; o += 8) u = fmaf(w3[o], vw[o*C + c], u);
    red[t] = u;
    __syncthreads();
    if (t < 32) {
        float s = 0.f;
        #pragma unroll
        for (int k2 = 0; k2 < 8; k2++) s += red[(k2 << 5) + t];
        g_u[(blockIdx.x << 5) + t] = s;
    }
    if (blockIdx.x == 0) {
        __syncthreads();
        red[t] = w3[t] * vb[t];
        __syncthreads();
        if (t < 32) {
            float s = 0.f;
            #pragma unroll
            for (int k2 = 0; k2 < 8; k2++) s += red[(k2 << 5) + t];
            #pragma unroll
            for (int o = 16; o; o >>= 1) s += __shfl_down_sync(0xffffffffu, s, o);
            if (t == 0) g_ub = s;
        }
    }
}

// ---------- kB: main reduction pass — register-resident ----------
__global__ void __launch_bounds__(256, 4) kB(const float* __restrict__ x,
                                             const float* __restrict__ kw) {
    __shared__ float wsh[C], ush[C];
    __shared__ float red[4*256];
    __shared__ float esh[WC];

    int t = threadIdx.x, lane = t & 31, wid = t >> 5;
    int h = blockIdx.x, chunk = blockIdx.y, b = blockIdx.z;
    wsh[t] = kw[t];
    ush[t] = g_u[t];
    __syncthreads();

    int cloc = lane >> 3, w4 = lane & 7;
    int c0 = (wid << 5) + (cloc << 3);
    const float4* xp = (const float4*)(x + (((size_t)(b*C + c0)) << 14)
                                         + (h << 7) + (chunk << 5)) + w4;

    float4 v[8];
    #pragma unroll
    for (int j = 0; j < 8; j++) v[j] = __ldcs(xp + ((size_t)j << 12));  // +j*HW/4

    float kl[4] = {0,0,0,0}, t3[4] = {0,0,0,0}, sm[4] = {0,0,0,0};
    float mx[4] = {-1e30f,-1e30f,-1e30f,-1e30f};
    #pragma unroll
    for (int j = 0; j < 8; j++) {
        int c = c0 + j;
        float kc = wsh[c], uc = ush[c];
        kl[0]=fmaf(kc,v[j].x,kl[0]); kl[1]=fmaf(kc,v[j].y,kl[1]); kl[2]=fmaf(kc,v[j].z,kl[2]); kl[3]=fmaf(kc,v[j].w,kl[3]);
        t3[0]=fmaf(uc,v[j].x,t3[0]); t3[1]=fmaf(uc,v[j].y,t3[1]); t3[2]=fmaf(uc,v[j].z,t3[2]); t3[3]=fmaf(uc,v[j].w,t3[3]);
        mx[0]=fmaxf(mx[0],v[j].x); mx[1]=fmaxf(mx[1],v[j].y); mx[2]=fmaxf(mx[2],v[j].z); mx[3]=fmaxf(mx[3],v[j].w);
        sm[0]+=v[j].x; sm[1]+=v[j].y; sm[2]+=v[j].z; sm[3]+=v[j].w;
    }
    #pragma unroll
    for (int o = 16; o >= 8; o >>= 1) {
        #pragma unroll
        for (int l = 0; l < 4; l++) {
            kl[l] += __shfl_down_sync(0xffffffffu, kl[l], o);
            t3[l] += __shfl_down_sync(0xffffffffu, t3[l], o);
            mx[l] = fmaxf(mx[l], __shfl_down_sync(0xffffffffu, mx[l], o));
            sm[l] += __shfl_down_sync(0xffffffffu, sm[l], o);
        }
    }
    if (lane < 8) {
        int base = (wid << 5) + (lane << 2);
        #pragma unroll
        for (int l = 0; l < 4; l++) {
            red[base + l]       = kl[l];
            red[256 + base + l] = t3[l];
            red[512 + base + l] = mx[l];
            red[768 + base + l] = sm[l];
        }
    }
    __syncthreads();

    int bh = (b << 7) + h;
    int ci = (bh << 2) + chunk;
    if (t < 32) {
        float klw = 0.f, t3w = 0.f, smw = 0.f, mxw = -1e30f;
        #pragma unroll
        for (int wp = 0; wp < 8; wp++) {
            klw += red[(wp << 5) + t];
            t3w += red[256 + (wp << 5) + t];
            mxw = fmaxf(mxw, red[512 + (wp << 5) + t]);
            smw += red[768 + (wp << 5) + t];
        }
        float e = __expf(klw);                    // klin ~ N(0,1): no shift needed
        esh[t] = e;
        int gi = (bh << 7) + (chunk << 5) + t;
        g_t3[gi]   = t3w + g_ub;
        g_cmax[gi] = mxw;
        g_csum[gi] = smw;
        float rm = mxw, rs = smw, rz = e;
        #pragma unroll
        for (int o = 16; o; o >>= 1) {
            rm = fmaxf(rm, __shfl_down_sync(0xffffffffu, rm, o));
            rs += __shfl_down_sync(0xffffffffu, rs, o);
            rz += __shfl_down_sync(0xffffffffu, rz, o);
        }
        if (t == 0) { g_hmaxp[ci] = rm; g_hsump[ci] = rs; g_Zp[ci] = rz; }
    }
    __syncthreads();

    // phase 2 (register-resident): xk[c] partial
    float e0 = esh[(w4 << 2) + 0], e1 = esh[(w4 << 2) + 1];
    float e2 = esh[(w4 << 2) + 2], e3 = esh[(w4 << 2) + 3];
    float xkp[8];
    #pragma unroll
    for (int j = 0; j < 8; j++)
        xkp[j] = fmaf(v[j].x, e0, fmaf(v[j].y, e1, fmaf(v[j].z, e2, v[j].w * e3)));
    #pragma unroll
    for (int o = 4; o; o >>= 1) {
        #pragma unroll
        for (int j = 0; j < 8; j++)
            xkp[j] += __shfl_down_sync(0xffffffffu, xkp[j], o);
    }
    if (w4 == 0) {
        float* dst = g_xkpart + (((size_t)ci) << 8) + c0;
        #pragma unroll
        for (int j = 0; j < 8; j++) dst[j] = xkp[j];
    }
}

// ---------- kM: merged stage-2 reductions (grid (16,B)) ----------
// slices 0-7: xkpart partial reduce -> g_xk2.
// slices 8-15: full column stats for 16 w columns -> g_watt + 16 g_hatt.
// slice 8 additionally reduces g_Zp -> g_invZ[b] (piggyback, overlapped).
__global__ void __launch_bounds__(256) kM(const float* __restrict__ w1,
                                          const float* __restrict__ b1,
                                          const float* __restrict__ w2,
                                          const float* __restrict__ b2) {
    int t = threadIdx.x;
    int slice = blockIdx.x, b = blockIdx.y;
    if (slice < 8) {
        const float* base = g_xkpart + ((size_t)((b << 9) + (slice << 6)) << 8);
        float acc = 0.f;
        #pragma unroll 8
        for (int i = 0; i < 64; i++) acc += base[((size_t)i << 8) + t];
        g_xk2[(((b << 3) + slice) << 8) + t] = acc;
    } else {
        __shared__ float rm[256], rs[256];
        __shared__ float zp[8];
        int s2 = slice - 8;
        int w0 = s2 << 4;                        // this block: 16 w columns
        int w = t & 15, hg = t >> 4;             // 16 h-groups of 8 rows

        float zval = 0.f;
        if (s2 == 0)
            zval = g_Zp[(b << 9) + t] + g_Zp[(b << 9) + 256 + t];

        const float* cm = g_cmax + ((size_t)b << 14) + w0 + w;
        const float* cs = g_csum + ((size_t)b << 14) + w0 + w;
        float wm = -1e30f, ws = 0.f;
        #pragma unroll
        for (int i = 0; i < 8; i++) {
            int r = (hg << 3) + i;
            wm = fmaxf(wm, cm[r << 7]);
            ws += cs[r << 7];
        }
        rm[t] = wm; rs[t] = ws;
        if (s2 == 0) {
            #pragma unroll
            for (int o = 16; o; o >>= 1) zval += __shfl_down_sync(0xffffffffu, zval, o);
            if ((t & 31) == 0) zp[t >> 5] = zval;
        }
        __syncthreads();
        if (s2 == 0 && t == 0)
            g_invZ[b] = 1.f / (zp[0]+zp[1]+zp[2]+zp[3]+zp[4]+zp[5]+zp[6]+zp[7]);
        if (t < 16) {
            float m = rm[t], s = rs[t];
            #pragma unroll
            for (int k = 1; k < 16; k++) {
                m = fmaxf(m, rm[(k << 4) + t]);
                s += rs[(k << 4) + t];
            }
            float wa = fmaf(w2[0], m, fmaf(w2[1], s * (1.f/32768.f), b2[0]));
            g_watt[(b << 7) + w0 + t] = 1.f / (1.f + __expf(-wa));

            int h = w0 + t;
            int i4 = ((b << 7) + h) << 2;
            float hm = fmaxf(fmaxf(g_hmaxp[i4], g_hmaxp[i4+1]),
                             fmaxf(g_hmaxp[i4+2], g_hmaxp[i4+3]));
            float hs = g_hsump[i4] + g_hsump[i4+1] + g_hsump[i4+2] + g_hsump[i4+3];
            float ha = fmaf(w1[0], hm, fmaf(w1[1], hs * (1.f/32768.f), b1[0]));
            g_hatt[(b << 7) + h] = 1.f / (1.f + __expf(-ha));
        }
    }
}

// ---------- kCF: cf = invZ*(v_w @ xksum) + v_b — syncless, warp-autonomous ----------
// Each warp builds the full xk in-register (lane l holds floats 4l..4l+3 and
// 128+4l..128+4l+3) from g_xk2 directly, then does 4 rows. No smem, no syncs.
__global__ void __launch_bounds__(256) kCF(const float* __restrict__ vw,
                                           const float* __restrict__ vb) {
    int t = threadIdx.x, lane = t & 31, wid = t >> 5;
    int og = blockIdx.x, b = blockIdx.y;

    float invZ = g_invZ[b];
    const float4* xk2 = (const float4*)g_xk2;
    float4 x0 = make_float4(0.f,0.f,0.f,0.f);
    float4 x1 = make_float4(0.f,0.f,0.f,0.f);
    #pragma unroll
    for (int s = 0; s < 8; s++) {
        size_t rb = ((size_t)((b << 3) + s)) << 6;      // row base in float4
        float4 a = xk2[rb + lane];
        float4 c = xk2[rb + 32 + lane];
        x0.x += a.x; x0.y += a.y; x0.z += a.z; x0.w += a.w;
        x1.x += c.x; x1.y += c.y; x1.z += c.z; x1.w += c.w;
    }

    const float4* vw4 = (const float4*)vw;
    #pragma unroll
    for (int k = 0; k < 4; k++) {
        int o = (og << 5) + (wid << 2) + k;
        float4 w0 = vw4[(o << 6) + lane];
        float4 w1v = vw4[(o << 6) + 32 + lane];
        float a = fmaf(w0.x, x0.x, fmaf(w0.y, x0.y, fmaf(w0.z, x0.z, w0.w * x0.w)));
        a = fmaf(w1v.x, x1.x, fmaf(w1v.y, x1.y, fmaf(w1v.z, x1.z, fmaf(w1v.w, x1.w, a))));
        #pragma unroll
        for (int o2 = 16; o2; o2 >>= 1) a += __shfl_down_sync(0xffffffffu, a, o2);
        if (lane == 0) g_cf[(b << 8) + o] = fmaf(invZ, a, vb[o]);
    }
}

// ---------- kE: fused gate + output, deep unroll. out = s*cf + x ----------
__global__ void __launch_bounds__(256) kE(const float* __restrict__ x,
                                          float* __restrict__ out,
                                          const float* __restrict__ b3) {
    __shared__ float4 s4sh[64];
    __shared__ float cfsh[64];
    int t = threadIdx.x;
    int blk = blockIdx.x;
    int b = blk >> 8, rest = blk & 255;
    int pc = rest >> 2, cq = rest & 3;
    int p0 = pc << 8;
    int cbase = cq << 6;
    if (t < 64) {
        cfsh[t] = g_cf[(b << 8) + cbase + t];
        float4 t3v = reinterpret_cast<const float4*>(g_t3)[(b << 12) + (p0 >> 2) + t];
        int p = p0 + (t << 2);
        float ha = g_hatt[(b << 7) + (p >> 7)];
        int w0 = p & 127;
        float bb = b3[0];
        float4 s4; float a;
        a = fmaf(ha + g_watt[(b<<7)+w0+0], t3v.x, bb); s4.x = 1.f/(1.f+__expf(-a));
        a = fmaf(ha + g_watt[(b<<7)+w0+1], t3v.y, bb); s4.y = 1.f/(1.f+__expf(-a));
        a = fmaf(ha + g_watt[(b<<7)+w0+2], t3v.z, bb); s4.z = 1.f/(1.f+__expf(-a));
        a = fmaf(ha + g_watt[(b<<7)+w0+3], t3v.w, bb); s4.w = 1.f/(1.f+__expf(-a));
        s4sh[t] = s4;
    }
    __syncthreads();

    int c_off = t >> 6, p4 = t & 63;
    const float4* xb = (const float4*)x + ((size_t)b << 20)
                       + ((size_t)cbase << 12) + (p0 >> 2) + p4;
    float4*       ob = (float4*)out     + ((size_t)b << 20)
                       + ((size_t)cbase << 12) + (p0 >> 2) + p4;
    float4 sv = s4sh[p4];
    // 16 iterations: batch 8 loads then 8 stores per pass (reduce DRAM r/w turnaround)
    #pragma unroll
    for (int pass = 0; pass < 2; pass++) {
        float4 xv[8];
        #pragma unroll
        for (int u2 = 0; u2 < 8; u2++) {
            int c = (pass << 5) + (u2 << 2) + c_off;
            xv[u2] = __ldcs(xb + ((size_t)c << 12));
        }
        #pragma unroll
        for (int u2 = 0; u2 < 8; u2++) {
            int c = (pass << 5) + (u2 << 2) + c_off;
            float cf = cfsh[c];
            float4 ov;
            ov.x = fmaf(sv.x, cf, xv[u2].x);
            ov.y = fmaf(sv.y, cf, xv[u2].y);
            ov.z = fmaf(sv.z, cf, xv[u2].z);
            ov.w = fmaf(sv.w, cf, xv[u2].w);
            __stcs(ob + ((size_t)c << 12), ov);
        }
    }
}

extern "C" void kernel_launch(void* const* d_in, const int* in_sizes, int n_in,
                              void* d_out, int out_size) {
    const float* x  = (const float*)d_in[0];
    const float* vw = (const float*)d_in[1];
    const float* vb = (const float*)d_in[2];
    const float* kw = (const float*)d_in[3];
    // d_in[4] = k_b: softmax shift-invariant, unused
    const float* w1 = (const float*)d_in[5];
    const float* b1 = (const float*)d_in[6];
    const float* w2 = (const float*)d_in[7];
    const float* b2 = (const float*)d_in[8];
    const float* w3 = (const float*)d_in[9];
    const float* b3 = (const float*)d_in[10];
    float* out = (float*)d_out;

    kA<<<8, 256>>>(vw, vb, w3);
    dim3 gB(H, NCH, B);
    kB<<<gB, 256>>>(x, kw);
    dim3 gM(16, B);
    kM<<<gM, 256>>>(w1, b1, w2, b2);
    dim3 gCF(8, B);
    kCF<<<gCF, 256>>>(vw, vb);
    kE<<<2048, 256>>>(x, out, b3);
}

// round 15
// speedup vs baseline: 1.0719x; 1.0253x over previous
#include <cuda_runtime.h>
#include <cuda_bf16.h>
#include <math_constants.h>

// x = [B=8, C=256, H=128, W=128] fp32
#define B 8
#define C 256
#define H 128
#define W 128
#define HW (H*W)
#define WC 32             // w-chunk per kB block
#define NCH 4             // W / WC

// ---------- scratch ----------
__device__ float g_u[C];
__device__ float g_ub;
__device__ __align__(16) float g_t3[B*HW];
__device__ __align__(16) float g_xkpart[B*H*NCH*C];   // [b][h][chunk][c]
__device__ __align__(16) float g_xk2[B*8*C];          // slice partials
__device__ float g_Zp[B*H*NCH];
__device__ float g_invZ[B];
__device__ float g_cmax[B*H*W];
__device__ float g_csum[B*H*W];
__device__ float g_hmaxp[B*H*NCH];
__device__ float g_hsump[B*H*NCH];
__device__ float g_hatt[B*H];
__device__ float g_watt[B*W];

// ---------- kA: u = w3^T v_w, ub = w3.v_b ----------
__global__ void __launch_bounds__(256) kA(const float* __restrict__ vw,
                                          const float* __restrict__ vb,
                                          const float* __restrict__ w3) {
    __shared__ float red[256];
    int t = threadIdx.x, lane = t & 31, g = t >> 5;
    int c = (blockIdx.x << 5) + lane;
    float u = 0.f;
    #pragma unroll
    for (int o = g; o < C; o += 8) u = fmaf(w3[o], vw[o*C + c], u);
    red[t] = u;
    __syncthreads();
    if (t < 32) {
        float s = 0.f;
        #pragma unroll
        for (int k2 = 0; k2 < 8; k2++) s += red[(k2 << 5) + t];
        g_u[(blockIdx.x << 5) + t] = s;
    }
    if (blockIdx.x == 0) {
        __syncthreads();
        red[t] = w3[t] * vb[t];
        __syncthreads();
        if (t < 32) {
            float s = 0.f;
            #pragma unroll
            for (int k2 = 0; k2 < 8; k2++) s += red[(k2 << 5) + t];
            #pragma unroll
            for (int o = 16; o; o >>= 1) s += __shfl_down_sync(0xffffffffu, s, o);
            if (t == 0) g_ub = s;
        }
    }
}

// ---------- kB: main reduction pass — register-resident ----------
__global__ void __launch_bounds__(256, 4) kB(const float* __restrict__ x,
                                             const float* __restrict__ kw) {
    __shared__ float wsh[C], ush[C];
    __shared__ float red[4*256];
    __shared__ float esh[WC];

    int t = threadIdx.x, lane = t & 31, wid = t >> 5;
    int h = blockIdx.x, chunk = blockIdx.y, b = blockIdx.z;
    wsh[t] = kw[t];
    ush[t] = g_u[t];
    __syncthreads();

    int cloc = lane >> 3, w4 = lane & 7;
    int c0 = (wid << 5) + (cloc << 3);
    const float4* xp = (const float4*)(x + (((size_t)(b*C + c0)) << 14)
                                         + (h << 7) + (chunk << 5)) + w4;

    float4 v[8];
    #pragma unroll
    for (int j = 0; j < 8; j++) v[j] = __ldcs(xp + ((size_t)j << 12));  // +j*HW/4

    float kl[4] = {0,0,0,0}, t3[4] = {0,0,0,0}, sm[4] = {0,0,0,0};
    float mx[4] = {-1e30f,-1e30f,-1e30f,-1e30f};
    #pragma unroll
    for (int j = 0; j < 8; j++) {
        int c = c0 + j;
        float kc = wsh[c], uc = ush[c];
        kl[0]=fmaf(kc,v[j].x,kl[0]); kl[1]=fmaf(kc,v[j].y,kl[1]); kl[2]=fmaf(kc,v[j].z,kl[2]); kl[3]=fmaf(kc,v[j].w,kl[3]);
        t3[0]=fmaf(uc,v[j].x,t3[0]); t3[1]=fmaf(uc,v[j].y,t3[1]); t3[2]=fmaf(uc,v[j].z,t3[2]); t3[3]=fmaf(uc,v[j].w,t3[3]);
        mx[0]=fmaxf(mx[0],v[j].x); mx[1]=fmaxf(mx[1],v[j].y); mx[2]=fmaxf(mx[2],v[j].z); mx[3]=fmaxf(mx[3],v[j].w);
        sm[0]+=v[j].x; sm[1]+=v[j].y; sm[2]+=v[j].z; sm[3]+=v[j].w;
    }
    #pragma unroll
    for (int o = 16; o >= 8; o >>= 1) {
        #pragma unroll
        for (int l = 0; l < 4; l++) {
            kl[l] += __shfl_down_sync(0xffffffffu, kl[l], o);
            t3[l] += __shfl_down_sync(0xffffffffu, t3[l], o);
            mx[l] = fmaxf(mx[l], __shfl_down_sync(0xffffffffu, mx[l], o));
            sm[l] += __shfl_down_sync(0xffffffffu, sm[l], o);
        }
    }
    if (lane < 8) {
        int base = (wid << 5) + (lane << 2);
        #pragma unroll
        for (int l = 0; l < 4; l++) {
            red[base + l]       = kl[l];
            red[256 + base + l] = t3[l];
            red[512 + base + l] = mx[l];
            red[768 + base + l] = sm[l];
        }
    }
    __syncthreads();

    int bh = (b << 7) + h;
    int ci = (bh << 2) + chunk;
    if (t < 32) {
        float klw = 0.f, t3w = 0.f, smw = 0.f, mxw = -1e30f;
        #pragma unroll
        for (int wp = 0; wp < 8; wp++) {
            klw += red[(wp << 5) + t];
            t3w += red[256 + (wp << 5) + t];
            mxw = fmaxf(mxw, red[512 + (wp << 5) + t]);
            smw += red[768 + (wp << 5) + t];
        }
        float e = __expf(klw);                    // klin ~ N(0,1): no shift needed
        esh[t] = e;
        int gi = (bh << 7) + (chunk << 5) + t;
        g_t3[gi]   = t3w + g_ub;
        g_cmax[gi] = mxw;
        g_csum[gi] = smw;
        float rm = mxw, rs = smw, rz = e;
        #pragma unroll
        for (int o = 16; o; o >>= 1) {
            rm = fmaxf(rm, __shfl_down_sync(0xffffffffu, rm, o));
            rs += __shfl_down_sync(0xffffffffu, rs, o);
            rz += __shfl_down_sync(0xffffffffu, rz, o);
        }
        if (t == 0) { g_hmaxp[ci] = rm; g_hsump[ci] = rs; g_Zp[ci] = rz; }
    }
    __syncthreads();

    // phase 2 (register-resident): xk[c] partial
    float e0 = esh[(w4 << 2) + 0], e1 = esh[(w4 << 2) + 1];
    float e2 = esh[(w4 << 2) + 2], e3 = esh[(w4 << 2) + 3];
    float xkp[8];
    #pragma unroll
    for (int j = 0; j < 8; j++)
        xkp[j] = fmaf(v[j].x, e0, fmaf(v[j].y, e1, fmaf(v[j].z, e2, v[j].w * e3)));
    #pragma unroll
    for (int o = 4; o; o >>= 1) {
        #pragma unroll
        for (int j = 0; j < 8; j++)
            xkp[j] += __shfl_down_sync(0xffffffffu, xkp[j], o);
    }
    if (w4 == 0) {
        float* dst = g_xkpart + (((size_t)ci) << 8) + c0;
        #pragma unroll
        for (int j = 0; j < 8; j++) dst[j] = xkp[j];
    }
}

// ---------- kM: merged stage-2 reductions (grid (16,B)) ----------
__global__ void __launch_bounds__(256) kM(const float* __restrict__ w1,
                                          const float* __restrict__ b1,
                                          const float* __restrict__ w2,
                                          const float* __restrict__ b2) {
    int t = threadIdx.x;
    int slice = blockIdx.x, b = blockIdx.y;
    if (slice < 8) {
        const float* base = g_xkpart + ((size_t)((b << 9) + (slice << 6)) << 8);
        float acc = 0.f;
        #pragma unroll 8
        for (int i = 0; i < 64; i++) acc += base[((size_t)i << 8) + t];
        g_xk2[(((b << 3) + slice) << 8) + t] = acc;
    } else {
        __shared__ float rm[256], rs[256];
        __shared__ float zp[8];
        int s2 = slice - 8;
        int w0 = s2 << 4;                        // this block: 16 w columns
        int w = t & 15, hg = t >> 4;             // 16 h-groups of 8 rows

        float zval = 0.f;
        if (s2 == 0)
            zval = g_Zp[(b << 9) + t] + g_Zp[(b << 9) + 256 + t];

        const float* cm = g_cmax + ((size_t)b << 14) + w0 + w;
        const float* cs = g_csum + ((size_t)b << 14) + w0 + w;
        float wm = -1e30f, ws = 0.f;
        #pragma unroll
        for (int i = 0; i < 8; i++) {
            int r = (hg << 3) + i;
            wm = fmaxf(wm, cm[r << 7]);
            ws += cs[r << 7];
        }
        rm[t] = wm; rs[t] = ws;
        if (s2 == 0) {
            #pragma unroll
            for (int o = 16; o; o >>= 1) zval += __shfl_down_sync(0xffffffffu, zval, o);
            if ((t & 31) == 0) zp[t >> 5] = zval;
        }
        __syncthreads();
        if (s2 == 0 && t == 0)
            g_invZ[b] = 1.f / (zp[0]+zp[1]+zp[2]+zp[3]+zp[4]+zp[5]+zp[6]+zp[7]);
        if (t < 16) {
            float m = rm[t], s = rs[t];
            #pragma unroll
            for (int k = 1; k < 16; k++) {
                m = fmaxf(m, rm[(k << 4) + t]);
                s += rs[(k << 4) + t];
            }
            float wa = fmaf(w2[0], m, fmaf(w2[1], s * (1.f/32768.f), b2[0]));
            g_watt[(b << 7) + w0 + t] = 1.f / (1.f + __expf(-wa));

            int h = w0 + t;
            int i4 = ((b << 7) + h) << 2;
            float hm = fmaxf(fmaxf(g_hmaxp[i4], g_hmaxp[i4+1]),
                             fmaxf(g_hmaxp[i4+2], g_hmaxp[i4+3]));
            float hs = g_hsump[i4] + g_hsump[i4+1] + g_hsump[i4+2] + g_hsump[i4+3];
            float ha = fmaf(w1[0], hm, fmaf(w1[1], hs * (1.f/32768.f), b1[0]));
            g_hatt[(b << 7) + h] = 1.f / (1.f + __expf(-ha));
        }
    }
}

// ---------- kE: gate + per-block cf + output. out = s*cf + x ----------
// kCF distributed into the prologue: each block computes its own 64 cf values.
// vw is L2-resident (256 KB) after the first wave -> pure L2 traffic, fully
// overlapped by the 2048-block streaming pipeline.
__global__ void __launch_bounds__(256) kE(const float* __restrict__ x,
                                          float* __restrict__ out,
                                          const float* __restrict__ vw,
                                          const float* __restrict__ vb,
                                          const float* __restrict__ b3) {
    __shared__ float4 s4sh[64];
    __shared__ float xksh[C];
    __shared__ float cfsh[64];
    int t = threadIdx.x, lane = t & 31, wid = t >> 5;
    int blk = blockIdx.x;
    int b = blk >> 8, rest = blk & 255;
    int pc = rest >> 2, cq = rest & 3;
    int p0 = pc << 8;
    int cbase = cq << 6;

    // phase A: assemble xk (all threads) + s-table (t<64), independent work
    float acc = 0.f;
    #pragma unroll
    for (int s = 0; s < 8; s++) acc += g_xk2[(((b << 3) + s) << 8) + t];
    xksh[t] = acc;
    if (t < 64) {
        float4 t3v = reinterpret_cast<const float4*>(g_t3)[(b << 12) + (p0 >> 2) + t];
        int p = p0 + (t << 2);
        float ha = g_hatt[(b << 7) + (p >> 7)];
        int w0 = p & 127;
        float bb = b3[0];
        float4 s4; float a;
        a = fmaf(ha + g_watt[(b<<7)+w0+0], t3v.x, bb); s4.x = 1.f/(1.f+__expf(-a));
        a = fmaf(ha + g_watt[(b<<7)+w0+1], t3v.y, bb); s4.y = 1.f/(1.f+__expf(-a));
        a = fmaf(ha + g_watt[(b<<7)+w0+2], t3v.z, bb); s4.z = 1.f/(1.f+__expf(-a));
        a = fmaf(ha + g_watt[(b<<7)+w0+3], t3v.w, bb); s4.w = 1.f/(1.f+__expf(-a));
        s4sh[t] = s4;
    }
    __syncthreads();

    // phase B: cf for this quarter's 64 channels (warp w -> 8 rows, coalesced)
    float invZ = g_invZ[b];
    const float4* vw4 = (const float4*)vw;
    const float4* xk4 = (const float4*)xksh;
    float4 x0 = xk4[lane];
    float4 x1 = xk4[32 + lane];
    #pragma unroll
    for (int r = 0; r < 8; r++) {
        int o = cbase + (wid << 3) + r;
        float4 w0v = vw4[(o << 6) + lane];
        float4 w1v = vw4[(o << 6) + 32 + lane];
        float a = fmaf(w0v.x, x0.x, fmaf(w0v.y, x0.y, fmaf(w0v.z, x0.z, w0v.w * x0.w)));
        a = fmaf(w1v.x, x1.x, fmaf(w1v.y, x1.y, fmaf(w1v.z, x1.z, fmaf(w1v.w, x1.w, a))));
        #pragma unroll
        for (int o2 = 16; o2; o2 >>= 1) a += __shfl_down_sync(0xffffffffu, a, o2);
        if (lane == 0) cfsh[(wid << 3) + r] = fmaf(invZ, a, vb[o]);
    }
    __syncthreads();

    // streaming: 64 channels x 256 pixels
    int c_off = t >> 6, p4 = t & 63;
    const float4* xb = (const float4*)x + ((size_t)b << 20)
                       + ((size_t)cbase << 12) + (p0 >> 2) + p4;
    float4*       ob = (float4*)out     + ((size_t)b << 20)
                       + ((size_t)cbase << 12) + (p0 >> 2) + p4;
    float4 sv = s4sh[p4];
    #pragma unroll
    for (int pass = 0; pass < 2; pass++) {
        float4 xv[8];
        #pragma unroll
        for (int u2 = 0; u2 < 8; u2++) {
            int c = (pass << 5) + (u2 << 2) + c_off;
            xv[u2] = __ldcs(xb + ((size_t)c << 12));
        }
        #pragma unroll
        for (int u2 = 0; u2 < 8; u2++) {
            int c = (pass << 5) + (u2 << 2) + c_off;
            float cf = cfsh[c];
            float4 ov;
            ov.x = fmaf(sv.x, cf, xv[u2].x);
            ov.y = fmaf(sv.y, cf, xv[u2].y);
            ov.z = fmaf(sv.z, cf, xv[u2].z);
            ov.w = fmaf(sv.w, cf, xv[u2].w);
            __stcs(ob + ((size_t)c << 12), ov);
        }
    }
}

extern "C" void kernel_launch(void* const* d_in, const int* in_sizes, int n_in,
                              void* d_out, int out_size) {
    const float* x  = (const float*)d_in[0];
    const float* vw = (const float*)d_in[1];
    const float* vb = (const float*)d_in[2];
    const float* kw = (const float*)d_in[3];
    // d_in[4] = k_b: softmax shift-invariant, unused
    const float* w1 = (const float*)d_in[5];
    const float* b1 = (const float*)d_in[6];
    const float* w2 = (const float*)d_in[7];
    const float* b2 = (const float*)d_in[8];
    const float* w3 = (const float*)d_in[9];
    const float* b3 = (const float*)d_in[10];
    float* out = (float*)d_out;

    kA<<<8, 256>>>(vw, vb, w3);
    dim3 gB(H, NCH, B);
    kB<<<gB, 256>>>(x, kw);
    dim3 gM(16, B);
    kM<<<gM, 256>>>(w1, b1, w2, b2);
    kE<<<2048, 256>>>(x, out, vw, vb, b3);
}